// round 1
// baseline (speedup 1.0000x reference)
#include <cuda_runtime.h>

// Problem constants (fixed shapes)
#define N_NODES 50000
#define T_STEPS 12
#define F_IN    128
#define HEADS   4
#define FILT    32
#define DDIM    128          // HEADS*FILT
#define E_EDGES 800000
#define NEG_SLOPE 0.2f
#define D3      (3 * DDIM)   // 384

// ---------------- scratch (device globals; no allocation in kernel_launch) ----------------
__device__ float d_h_feat[N_NODES * DDIM];     // h = x_t @ W_gat
__device__ float d_alS[N_NODES * HEADS];
__device__ float d_alD[N_NODES * HEADS];
__device__ float d_denom[N_NODES * HEADS];
__device__ float d_acc[N_NODES * DDIM];
__device__ float d_g[N_NODES * DDIM];          // relu'd GAT output
__device__ float d_gi[N_NODES * D3];
__device__ float d_gh[N_NODES * D3];
__device__ float d_hstate[N_NODES * DDIM];
__device__ float d_WihT[DDIM * D3];            // [k][j]
__device__ float d_WhhT[DDIM * D3];

// ---------------- small utility kernels ----------------
__global__ void zero_kernel(float* p, int n) {
    int i = blockIdx.x * blockDim.x + threadIdx.x;
    if (i < n) p[i] = 0.0f;
}

// WT[k*D3 + j] = W[j*DDIM + k]   (W is [3D, D] row-major)
__global__ void transpose_w(const float* __restrict__ W, float* __restrict__ WT) {
    int idx = blockIdx.x * blockDim.x + threadIdx.x;
    if (idx < D3 * DDIM) {
        int j = idx / DDIM;
        int k = idx - j * DDIM;
        WT[k * D3 + j] = W[idx];
    }
}

// ---------------- tiled SGEMM: C[m][c] = sum_k A[m][k] * W[k][c] (+bias[c]) ----------------
// A: row stride lda, K = 128 fixed. W: row-major [128][NO]. C: row-major [M][NO].
#define BM 64
#define BN 128
#define KDIM 128
#define KC 32

__global__ __launch_bounds__(256) void gemm_kernel(
    const float* __restrict__ A, int lda, int M,
    const float* __restrict__ W, int NO,
    const float* __restrict__ bias,
    float* __restrict__ C)
{
    __shared__ float Xs[BM][KC + 1];
    __shared__ float Ws[KC][BN];

    const int tid = threadIdx.x;
    const int tx = tid & 15;        // col group (8 cols each)
    const int ty = tid >> 4;        // row group (4 rows each)
    const int row0 = blockIdx.x * BM;
    const int c0 = blockIdx.y * BN;

    float acc[4][8];
#pragma unroll
    for (int i = 0; i < 4; i++)
#pragma unroll
        for (int j = 0; j < 8; j++) acc[i][j] = 0.0f;

    for (int k0 = 0; k0 < KDIM; k0 += KC) {
        // load X tile: 64 rows x 32 k
#pragma unroll
        for (int i = 0; i < 8; i++) {
            int lin = tid + i * 256;           // 0..2047
            int r = lin >> 5, kk = lin & 31;
            int gr = row0 + r;
            Xs[r][kk] = (gr < M) ? A[(long)gr * lda + k0 + kk] : 0.0f;
        }
        // load W tile: 32 k x 128 c (float4)
#pragma unroll
        for (int i = 0; i < 4; i++) {
            int lin = tid + i * 256;           // 0..1023 float4 slots
            int kk = lin >> 5, c4 = lin & 31;
            *(float4*)&Ws[kk][c4 * 4] =
                *(const float4*)&W[(long)(k0 + kk) * NO + c0 + c4 * 4];
        }
        __syncthreads();

#pragma unroll
        for (int kk = 0; kk < KC; kk++) {
            float4 wa = *(const float4*)&Ws[kk][tx * 8];
            float4 wb = *(const float4*)&Ws[kk][tx * 8 + 4];
            float wv[8] = {wa.x, wa.y, wa.z, wa.w, wb.x, wb.y, wb.z, wb.w};
            float xv[4];
#pragma unroll
            for (int i = 0; i < 4; i++) xv[i] = Xs[ty * 4 + i][kk];
#pragma unroll
            for (int i = 0; i < 4; i++)
#pragma unroll
                for (int j = 0; j < 8; j++)
                    acc[i][j] = fmaf(xv[i], wv[j], acc[i][j]);
        }
        __syncthreads();
    }

    float bb[8];
#pragma unroll
    for (int j = 0; j < 8; j++) bb[j] = bias ? bias[c0 + tx * 8 + j] : 0.0f;

#pragma unroll
    for (int i = 0; i < 4; i++) {
        int gr = row0 + ty * 4 + i;
        if (gr >= M) continue;
        float* cp = &C[(long)gr * NO + c0 + tx * 8];
        float4 o1 = {acc[i][0] + bb[0], acc[i][1] + bb[1], acc[i][2] + bb[2], acc[i][3] + bb[3]};
        float4 o2 = {acc[i][4] + bb[4], acc[i][5] + bb[5], acc[i][6] + bb[6], acc[i][7] + bb[7]};
        *(float4*)cp = o1;
        *(float4*)(cp + 4) = o2;
    }
}

// ---------------- per-node init: attention logits + self-loop contribution ----------------
// one warp per node. lane l handles cols [4l, 4l+4). head = l>>3.
__global__ __launch_bounds__(256) void node_init(
    const float* __restrict__ h,
    const float* __restrict__ a_src, const float* __restrict__ a_dst,
    float* __restrict__ alS, float* __restrict__ alD,
    float* __restrict__ denom, float* __restrict__ acc)
{
    int warp = (blockIdx.x * blockDim.x + threadIdx.x) >> 5;
    int lane = threadIdx.x & 31;
    if (warp >= N_NODES) return;
    int n = warp;
    int head = lane >> 3;
    int sub = lane & 7;

    float4 hv = ((const float4*)h)[n * 32 + lane];
    float4 a1 = ((const float4*)a_src)[head * 8 + sub];
    float4 a2 = ((const float4*)a_dst)[head * 8 + sub];
    float s = hv.x * a1.x + hv.y * a1.y + hv.z * a1.z + hv.w * a1.w;
    float d = hv.x * a2.x + hv.y * a2.y + hv.z * a2.z + hv.w * a2.w;
    // reduce within 8-lane head group
#pragma unroll
    for (int off = 4; off > 0; off >>= 1) {
        s += __shfl_down_sync(0xffffffffu, s, off, 8);
        d += __shfl_down_sync(0xffffffffu, d, off, 8);
    }
    float sg = __shfl_sync(0xffffffffu, s, 0, 8);   // broadcast group leader
    float dg = __shfl_sync(0xffffffffu, d, 0, 8);

    float v = sg + dg;                               // self-loop logit
    float e = v > 0.0f ? v : NEG_SLOPE * v;
    float w = __expf(e);
    if (sub == 0) {
        alS[n * HEADS + head] = sg;
        alD[n * HEADS + head] = dg;
        denom[n * HEADS + head] = w;                 // self-loop term
    }
    float4 o = {w * hv.x, w * hv.y, w * hv.z, w * hv.w};
    ((float4*)acc)[n * 32 + lane] = o;               // self-loop message
}

// ---------------- edge pass: one warp per edge ----------------
__global__ __launch_bounds__(256) void edge_kernel(
    const int* __restrict__ src_arr, const int* __restrict__ dst_arr,
    const float* __restrict__ alS, const float* __restrict__ alD,
    const float* __restrict__ h,
    float* __restrict__ denom, float* __restrict__ acc)
{
    long gw = (long)blockIdx.x * (blockDim.x >> 5) + (threadIdx.x >> 5);
    if (gw >= E_EDGES) return;
    int lane = threadIdx.x & 31;
    int head = lane >> 3;

    int s = src_arr[gw];
    int d = dst_arr[gw];

    float v = alS[s * HEADS + head] + alD[d * HEADS + head];
    float e = v > 0.0f ? v : NEG_SLOPE * v;
    float w = __expf(e);

    if ((lane & 7) == 0) atomicAdd(&denom[d * HEADS + head], w);

    float4 hv = ((const float4*)h)[s * 32 + lane];
    float* ap = &acc[d * DDIM + lane * 4];
    atomicAdd(ap + 0, w * hv.x);
    atomicAdd(ap + 1, w * hv.y);
    atomicAdd(ap + 2, w * hv.z);
    atomicAdd(ap + 3, w * hv.w);
}

// ---------------- finalize GAT: g = relu(acc/denom + b_gat) ----------------
__global__ void finalize_gat(
    const float* __restrict__ acc, const float* __restrict__ denom,
    const float* __restrict__ bg, float* __restrict__ g)
{
    int idx = blockIdx.x * blockDim.x + threadIdx.x;   // over N*32 float4s
    if (idx >= N_NODES * 32) return;
    int n = idx >> 5;
    int c4 = idx & 31;
    int head = c4 >> 3;
    float inv = 1.0f / (denom[n * HEADS + head] + 1e-16f);
    float4 a = ((const float4*)acc)[idx];
    float4 b = ((const float4*)bg)[c4];
    float4 o;
    o.x = fmaxf(a.x * inv + b.x, 0.0f);
    o.y = fmaxf(a.y * inv + b.y, 0.0f);
    o.z = fmaxf(a.z * inv + b.z, 0.0f);
    o.w = fmaxf(a.w * inv + b.w, 0.0f);
    ((float4*)g)[idx] = o;
}

// ---------------- GRU gates: h = (1-z)*n + z*h ----------------
__global__ void gru_gates(
    const float* __restrict__ gi, const float* __restrict__ gh,
    float* __restrict__ h)
{
    int idx = blockIdx.x * blockDim.x + threadIdx.x;   // over N*DDIM
    if (idx >= N_NODES * DDIM) return;
    int n = idx >> 7;
    int c = idx & 127;
    long base = (long)n * D3;
    float ir = gi[base + c],        hr = gh[base + c];
    float iz = gi[base + 128 + c],  hz = gh[base + 128 + c];
    float in_ = gi[base + 256 + c], hn = gh[base + 256 + c];
    float r = 1.0f / (1.0f + __expf(-(ir + hr)));
    float z = 1.0f / (1.0f + __expf(-(iz + hz)));
    float nn = tanhf(in_ + r * hn);
    h[idx] = (1.0f - z) * nn + z * h[idx];
}

// ---------------- final linear: out[n] = h[n] . W_lin + b_lin ----------------
__global__ __launch_bounds__(256) void final_linear(
    const float* __restrict__ h, const float* __restrict__ Wl,
    const float* __restrict__ bl, float* __restrict__ out)
{
    int warp = (blockIdx.x * blockDim.x + threadIdx.x) >> 5;
    int lane = threadIdx.x & 31;
    if (warp >= N_NODES) return;
    float4 hv = ((const float4*)h)[warp * 32 + lane];
    float4 wv = ((const float4*)Wl)[lane];
    float s = hv.x * wv.x + hv.y * wv.y + hv.z * wv.z + hv.w * wv.w;
#pragma unroll
    for (int off = 16; off > 0; off >>= 1)
        s += __shfl_down_sync(0xffffffffu, s, off);
    if (lane == 0) out[warp] = s + bl[0];
}

// ---------------- launcher ----------------
extern "C" void kernel_launch(void* const* d_in, const int* in_sizes, int n_in,
                              void* d_out, int out_size)
{
    const float* x   = (const float*)d_in[0];   // [N,T,F_IN]
    const int*   ei  = (const int*)d_in[1];     // [T,2,E]
    const float* Wg  = (const float*)d_in[2];   // [128,128]
    const float* as  = (const float*)d_in[3];   // [4,32]
    const float* ad  = (const float*)d_in[4];   // [4,32]
    const float* bg  = (const float*)d_in[5];   // [128]
    const float* Wih = (const float*)d_in[6];   // [384,128]
    const float* Whh = (const float*)d_in[7];   // [384,128]
    const float* bih = (const float*)d_in[8];   // [384]
    const float* bhh = (const float*)d_in[9];   // [384]
    const float* Wl  = (const float*)d_in[10];  // [1,128]
    const float* bl  = (const float*)d_in[11];  // [1]
    float* out = (float*)d_out;

    float *h_feat, *alS, *alD, *denom, *acc, *g, *gi, *gh, *hstate, *WihT, *WhhT;
    cudaGetSymbolAddress((void**)&h_feat, d_h_feat);
    cudaGetSymbolAddress((void**)&alS,    d_alS);
    cudaGetSymbolAddress((void**)&alD,    d_alD);
    cudaGetSymbolAddress((void**)&denom,  d_denom);
    cudaGetSymbolAddress((void**)&acc,    d_acc);
    cudaGetSymbolAddress((void**)&g,      d_g);
    cudaGetSymbolAddress((void**)&gi,     d_gi);
    cudaGetSymbolAddress((void**)&gh,     d_gh);
    cudaGetSymbolAddress((void**)&hstate, d_hstate);
    cudaGetSymbolAddress((void**)&WihT,   d_WihT);
    cudaGetSymbolAddress((void**)&WhhT,   d_WhhT);

    const int GEMM_GX = (N_NODES + BM - 1) / BM;   // 782

    // prologue: zero hidden state, transpose GRU weights
    zero_kernel<<<(N_NODES * DDIM + 255) / 256, 256>>>(hstate, N_NODES * DDIM);
    transpose_w<<<(D3 * DDIM + 255) / 256, 256>>>(Wih, WihT);
    transpose_w<<<(D3 * DDIM + 255) / 256, 256>>>(Whh, WhhT);

    for (int t = 0; t < T_STEPS; t++) {
        // 1) h = x_t @ W_gat
        gemm_kernel<<<dim3(GEMM_GX, 1), 256>>>(
            x + (long)t * F_IN, T_STEPS * F_IN, N_NODES, Wg, DDIM, nullptr, h_feat);

        // 2) attention logits + self-loop init of denom/acc
        node_init<<<(N_NODES * 32 + 255) / 256, 256>>>(h_feat, as, ad, alS, alD, denom, acc);

        // 3) single edge pass (unnormalized softmax accumulation)
        const int* src = ei + (long)t * 2 * E_EDGES;
        const int* dst = src + E_EDGES;
        edge_kernel<<<(E_EDGES * 32 + 255) / 256, 256>>>(src, dst, alS, alD, h_feat, denom, acc);

        // 4) g = relu(acc/denom + b_gat)
        finalize_gat<<<(N_NODES * 32 + 255) / 256, 256>>>(acc, denom, bg, g);

        // 5) gi = g @ W_ih.T + b_ih ;  gh = h @ W_hh.T + b_hh
        gemm_kernel<<<dim3(GEMM_GX, 3), 256>>>(g, DDIM, N_NODES, WihT, D3, bih, gi);
        gemm_kernel<<<dim3(GEMM_GX, 3), 256>>>(hstate, DDIM, N_NODES, WhhT, D3, bhh, gh);

        // 6) GRU update
        gru_gates<<<(N_NODES * DDIM + 255) / 256, 256>>>(gi, gh, hstate);
    }

    // final projection
    final_linear<<<(N_NODES * 32 + 255) / 256, 256>>>(hstate, Wl, bl, out);
}

// round 2
// speedup vs baseline: 1.6195x; 1.6195x over previous
#include <cuda_runtime.h>
#include <cstdint>

// Problem constants (fixed shapes)
#define N_NODES 50000
#define T_STEPS 12
#define F_IN    128
#define HEADS   4
#define FILT    32
#define DDIM    128          // HEADS*FILT
#define E_EDGES 800000
#define NEG_SLOPE 0.2f
#define D3      (3 * DDIM)   // 384

// ---------------- scratch (device globals; no allocation in kernel_launch) ----------------
__device__ float d_h_feat[N_NODES * DDIM];     // h = x_t @ W_gat
__device__ float d_alS[N_NODES * HEADS];
__device__ float d_alD[N_NODES * HEADS];
__device__ float d_denom[N_NODES * HEADS];
__device__ float d_acc[N_NODES * DDIM];
__device__ float d_g[N_NODES * DDIM];          // relu'd GAT output
__device__ float d_gi[N_NODES * D3];
__device__ float d_gh[N_NODES * D3];
__device__ float d_hstate[N_NODES * DDIM];
__device__ float d_WihT[DDIM * D3];            // [k][j]
__device__ float d_WhhT[DDIM * D3];

// ---------------- small utility kernels ----------------
__global__ void zero_kernel(float* p, int n) {
    int i = blockIdx.x * blockDim.x + threadIdx.x;
    if (i < n) p[i] = 0.0f;
}

// WT[k*D3 + j] = W[j*DDIM + k]   (W is [3D, D] row-major)
__global__ void transpose_w(const float* __restrict__ W, float* __restrict__ WT) {
    int idx = blockIdx.x * blockDim.x + threadIdx.x;
    if (idx < D3 * DDIM) {
        int j = idx / DDIM;
        int k = idx - j * DDIM;
        WT[k * D3 + j] = W[idx];
    }
}

// ---------------- tf32 tensor-core GEMM ----------------
// C[m][c] = sum_k A[m][k] * W[k][c] (+bias[c]),  K = 128 fixed.
// Block tile 128x128, KC=32. 8 warps, each computes 32 rows x 64 cols
// via 2 (m) x 8 (n) mma.sync.m16n8k8 fragments.

__device__ __forceinline__ float tf32r(float x) {
    uint32_t u;
    asm("cvt.rna.tf32.f32 %0, %1;" : "=r"(u) : "f"(x));
    return __uint_as_float(u);
}

__device__ __forceinline__ void mma16n8k8(float* c, const uint32_t* a, const uint32_t* b) {
    asm volatile(
        "mma.sync.aligned.m16n8k8.row.col.f32.tf32.tf32.f32 "
        "{%0,%1,%2,%3}, {%4,%5,%6,%7}, {%8,%9}, {%0,%1,%2,%3};\n"
        : "+f"(c[0]), "+f"(c[1]), "+f"(c[2]), "+f"(c[3])
        : "r"(a[0]), "r"(a[1]), "r"(a[2]), "r"(a[3]), "r"(b[0]), "r"(b[1]));
}

__global__ __launch_bounds__(256) void gemm_tf32(
    const float* __restrict__ A, int lda, int M,
    const float* __restrict__ W, int NO,
    const float* __restrict__ bias,
    float* __restrict__ C)
{
    __shared__ float As[128][36];   // [m][k], stride 36: conflict-free frag loads
    __shared__ float Ws[32][132];   // [k][n], stride 132: conflict-free frag loads

    const int tid  = threadIdx.x;
    const int lane = tid & 31;
    const int wid  = tid >> 5;
    const int wm   = (wid & 3) * 32;   // warp row base within block
    const int wn   = (wid >> 2) * 64;  // warp col base within block
    const int row0 = blockIdx.x * 128;
    const int c0   = blockIdx.y * 128;

    float cacc[2][8][4];
#pragma unroll
    for (int mf = 0; mf < 2; mf++)
#pragma unroll
        for (int nf = 0; nf < 8; nf++)
#pragma unroll
            for (int q = 0; q < 4; q++) cacc[mf][nf][q] = 0.0f;

    const int lq = lane >> 2;   // 0..7
    const int lr = lane & 3;    // 0..3

    for (int k0 = 0; k0 < 128; k0 += 32) {
        __syncthreads();
        // A tile: 128 rows x 32 k  (1024 float4 slots, 4 per thread)
#pragma unroll
        for (int i = 0; i < 4; i++) {
            int f = tid + i * 256;
            int r = f >> 3, kq = f & 7;
            int gr = row0 + r;
            float4 v = make_float4(0.f, 0.f, 0.f, 0.f);
            if (gr < M) v = *(const float4*)&A[(long)gr * lda + k0 + kq * 4];
            float4 cv = make_float4(tf32r(v.x), tf32r(v.y), tf32r(v.z), tf32r(v.w));
            *(float4*)&As[r][kq * 4] = cv;
        }
        // W tile: 32 k x 128 cols (1024 float4 slots, 4 per thread)
#pragma unroll
        for (int i = 0; i < 4; i++) {
            int f = tid + i * 256;
            int kk = f >> 5, c4 = f & 31;
            float4 v = *(const float4*)&W[(long)(k0 + kk) * NO + c0 + c4 * 4];
            float4 cv = make_float4(tf32r(v.x), tf32r(v.y), tf32r(v.z), tf32r(v.w));
            *(float4*)&Ws[kk][c4 * 4] = cv;
        }
        __syncthreads();

#pragma unroll
        for (int s = 0; s < 4; s++) {
            const int ks = s * 8;
            uint32_t af[2][4];
#pragma unroll
            for (int mf = 0; mf < 2; mf++) {
                int r = wm + mf * 16 + lq;
                int kc = ks + lr;
                af[mf][0] = __float_as_uint(As[r][kc]);
                af[mf][1] = __float_as_uint(As[r + 8][kc]);
                af[mf][2] = __float_as_uint(As[r][kc + 4]);
                af[mf][3] = __float_as_uint(As[r + 8][kc + 4]);
            }
            uint32_t bf[8][2];
#pragma unroll
            for (int nf = 0; nf < 8; nf++) {
                int cc = wn + nf * 8 + lq;
                int kr = ks + lr;
                bf[nf][0] = __float_as_uint(Ws[kr][cc]);
                bf[nf][1] = __float_as_uint(Ws[kr + 4][cc]);
            }
#pragma unroll
            for (int mf = 0; mf < 2; mf++)
#pragma unroll
                for (int nf = 0; nf < 8; nf++)
                    mma16n8k8(cacc[mf][nf], af[mf], bf[nf]);
        }
    }

    // epilogue: bias + store (float2 per row pair)
#pragma unroll
    for (int mf = 0; mf < 2; mf++) {
        int r_b = row0 + wm + mf * 16 + lq;
#pragma unroll
        for (int nf = 0; nf < 8; nf++) {
            int cc = c0 + wn + nf * 8 + lr * 2;
            float b0 = bias ? bias[cc] : 0.0f;
            float b1 = bias ? bias[cc + 1] : 0.0f;
            if (r_b < M) {
                float2 o = make_float2(cacc[mf][nf][0] + b0, cacc[mf][nf][1] + b1);
                *(float2*)&C[(long)r_b * NO + cc] = o;
            }
            if (r_b + 8 < M) {
                float2 o = make_float2(cacc[mf][nf][2] + b0, cacc[mf][nf][3] + b1);
                *(float2*)&C[(long)(r_b + 8) * NO + cc] = o;
            }
        }
    }
}

// ---------------- per-node init: attention logits + self-loop contribution ----------------
__global__ __launch_bounds__(256) void node_init(
    const float* __restrict__ h,
    const float* __restrict__ a_src, const float* __restrict__ a_dst,
    float* __restrict__ alS, float* __restrict__ alD,
    float* __restrict__ denom, float* __restrict__ acc)
{
    int warp = (blockIdx.x * blockDim.x + threadIdx.x) >> 5;
    int lane = threadIdx.x & 31;
    if (warp >= N_NODES) return;
    int n = warp;
    int head = lane >> 3;
    int sub = lane & 7;

    float4 hv = ((const float4*)h)[n * 32 + lane];
    float4 a1 = ((const float4*)a_src)[head * 8 + sub];
    float4 a2 = ((const float4*)a_dst)[head * 8 + sub];
    float s = hv.x * a1.x + hv.y * a1.y + hv.z * a1.z + hv.w * a1.w;
    float d = hv.x * a2.x + hv.y * a2.y + hv.z * a2.z + hv.w * a2.w;
#pragma unroll
    for (int off = 4; off > 0; off >>= 1) {
        s += __shfl_down_sync(0xffffffffu, s, off, 8);
        d += __shfl_down_sync(0xffffffffu, d, off, 8);
    }
    float sg = __shfl_sync(0xffffffffu, s, 0, 8);
    float dg = __shfl_sync(0xffffffffu, d, 0, 8);

    float v = sg + dg;                               // self-loop logit
    float e = v > 0.0f ? v : NEG_SLOPE * v;
    float w = __expf(e);
    if (sub == 0) {
        alS[n * HEADS + head] = sg;
        alD[n * HEADS + head] = dg;
        denom[n * HEADS + head] = w;                 // self-loop term
    }
    float4 o = {w * hv.x, w * hv.y, w * hv.z, w * hv.w};
    ((float4*)acc)[n * 32 + lane] = o;               // self-loop message
}

// ---------------- edge pass: one warp per edge ----------------
__global__ __launch_bounds__(256) void edge_kernel(
    const int* __restrict__ src_arr, const int* __restrict__ dst_arr,
    const float* __restrict__ alS, const float* __restrict__ alD,
    const float* __restrict__ h,
    float* __restrict__ denom, float* __restrict__ acc)
{
    long gw = (long)blockIdx.x * (blockDim.x >> 5) + (threadIdx.x >> 5);
    if (gw >= E_EDGES) return;
    int lane = threadIdx.x & 31;
    int head = lane >> 3;

    int s = src_arr[gw];
    int d = dst_arr[gw];

    float v = alS[s * HEADS + head] + alD[d * HEADS + head];
    float e = v > 0.0f ? v : NEG_SLOPE * v;
    float w = __expf(e);

    if ((lane & 7) == 0) atomicAdd(&denom[d * HEADS + head], w);

    float4 hv = ((const float4*)h)[s * 32 + lane];
    float* ap = &acc[d * DDIM + lane * 4];
    atomicAdd(ap + 0, w * hv.x);
    atomicAdd(ap + 1, w * hv.y);
    atomicAdd(ap + 2, w * hv.z);
    atomicAdd(ap + 3, w * hv.w);
}

// ---------------- finalize GAT: g = relu(acc/denom + b_gat) ----------------
__global__ void finalize_gat(
    const float* __restrict__ acc, const float* __restrict__ denom,
    const float* __restrict__ bg, float* __restrict__ g)
{
    int idx = blockIdx.x * blockDim.x + threadIdx.x;   // over N*32 float4s
    if (idx >= N_NODES * 32) return;
    int n = idx >> 5;
    int c4 = idx & 31;
    int head = c4 >> 3;
    float inv = 1.0f / (denom[n * HEADS + head] + 1e-16f);
    float4 a = ((const float4*)acc)[idx];
    float4 b = ((const float4*)bg)[c4];
    float4 o;
    o.x = fmaxf(a.x * inv + b.x, 0.0f);
    o.y = fmaxf(a.y * inv + b.y, 0.0f);
    o.z = fmaxf(a.z * inv + b.z, 0.0f);
    o.w = fmaxf(a.w * inv + b.w, 0.0f);
    ((float4*)g)[idx] = o;
}

// ---------------- GRU gates: h = (1-z)*n + z*h ----------------
__global__ void gru_gates(
    const float* __restrict__ gi, const float* __restrict__ gh,
    float* __restrict__ h)
{
    int idx = blockIdx.x * blockDim.x + threadIdx.x;   // over N*DDIM
    if (idx >= N_NODES * DDIM) return;
    int n = idx >> 7;
    int c = idx & 127;
    long base = (long)n * D3;
    float ir = gi[base + c],        hr = gh[base + c];
    float iz = gi[base + 128 + c],  hz = gh[base + 128 + c];
    float in_ = gi[base + 256 + c], hn = gh[base + 256 + c];
    float r = 1.0f / (1.0f + __expf(-(ir + hr)));
    float z = 1.0f / (1.0f + __expf(-(iz + hz)));
    float nn = tanhf(in_ + r * hn);
    h[idx] = (1.0f - z) * nn + z * h[idx];
}

// ---------------- final linear: out[n] = h[n] . W_lin + b_lin ----------------
__global__ __launch_bounds__(256) void final_linear(
    const float* __restrict__ h, const float* __restrict__ Wl,
    const float* __restrict__ bl, float* __restrict__ out)
{
    int warp = (blockIdx.x * blockDim.x + threadIdx.x) >> 5;
    int lane = threadIdx.x & 31;
    if (warp >= N_NODES) return;
    float4 hv = ((const float4*)h)[warp * 32 + lane];
    float4 wv = ((const float4*)Wl)[lane];
    float s = hv.x * wv.x + hv.y * wv.y + hv.z * wv.z + hv.w * wv.w;
#pragma unroll
    for (int off = 16; off > 0; off >>= 1)
        s += __shfl_down_sync(0xffffffffu, s, off);
    if (lane == 0) out[warp] = s + bl[0];
}

// ---------------- launcher ----------------
extern "C" void kernel_launch(void* const* d_in, const int* in_sizes, int n_in,
                              void* d_out, int out_size)
{
    const float* x   = (const float*)d_in[0];   // [N,T,F_IN]
    const int*   ei  = (const int*)d_in[1];     // [T,2,E]
    const float* Wg  = (const float*)d_in[2];   // [128,128]
    const float* as  = (const float*)d_in[3];   // [4,32]
    const float* ad  = (const float*)d_in[4];   // [4,32]
    const float* bg  = (const float*)d_in[5];   // [128]
    const float* Wih = (const float*)d_in[6];   // [384,128]
    const float* Whh = (const float*)d_in[7];   // [384,128]
    const float* bih = (const float*)d_in[8];   // [384]
    const float* bhh = (const float*)d_in[9];   // [384]
    const float* Wl  = (const float*)d_in[10];  // [1,128]
    const float* bl  = (const float*)d_in[11];  // [1]
    float* out = (float*)d_out;

    float *h_feat, *alS, *alD, *denom, *acc, *g, *gi, *gh, *hstate, *WihT, *WhhT;
    cudaGetSymbolAddress((void**)&h_feat, d_h_feat);
    cudaGetSymbolAddress((void**)&alS,    d_alS);
    cudaGetSymbolAddress((void**)&alD,    d_alD);
    cudaGetSymbolAddress((void**)&denom,  d_denom);
    cudaGetSymbolAddress((void**)&acc,    d_acc);
    cudaGetSymbolAddress((void**)&g,      d_g);
    cudaGetSymbolAddress((void**)&gi,     d_gi);
    cudaGetSymbolAddress((void**)&gh,     d_gh);
    cudaGetSymbolAddress((void**)&hstate, d_hstate);
    cudaGetSymbolAddress((void**)&WihT,   d_WihT);
    cudaGetSymbolAddress((void**)&WhhT,   d_WhhT);

    const int GX = (N_NODES + 127) / 128;   // 391

    // prologue: zero hidden state, transpose GRU weights
    zero_kernel<<<(N_NODES * DDIM + 255) / 256, 256>>>(hstate, N_NODES * DDIM);
    transpose_w<<<(D3 * DDIM + 255) / 256, 256>>>(Wih, WihT);
    transpose_w<<<(D3 * DDIM + 255) / 256, 256>>>(Whh, WhhT);

    for (int t = 0; t < T_STEPS; t++) {
        // 1) h = x_t @ W_gat  (tf32 tensor cores)
        gemm_tf32<<<dim3(GX, 1), 256>>>(
            x + (long)t * F_IN, T_STEPS * F_IN, N_NODES, Wg, DDIM, nullptr, h_feat);

        // 2) attention logits + self-loop init of denom/acc
        node_init<<<(N_NODES * 32 + 255) / 256, 256>>>(h_feat, as, ad, alS, alD, denom, acc);

        // 3) single edge pass (unnormalized softmax accumulation)
        const int* src = ei + (long)t * 2 * E_EDGES;
        const int* dst = src + E_EDGES;
        edge_kernel<<<(E_EDGES * 32 + 255) / 256, 256>>>(src, dst, alS, alD, h_feat, denom, acc);

        // 4) g = relu(acc/denom + b_gat)
        finalize_gat<<<(N_NODES * 32 + 255) / 256, 256>>>(acc, denom, bg, g);

        // 5) gi = g @ W_ih.T + b_ih ;  gh = h @ W_hh.T + b_hh  (tf32 tensor cores)
        gemm_tf32<<<dim3(GX, 3), 256>>>(g, DDIM, N_NODES, WihT, D3, bih, gi);
        gemm_tf32<<<dim3(GX, 3), 256>>>(hstate, DDIM, N_NODES, WhhT, D3, bhh, gh);

        // 6) GRU update
        gru_gates<<<(N_NODES * DDIM + 255) / 256, 256>>>(gi, gh, hstate);
    }

    // final projection
    final_linear<<<(N_NODES * 32 + 255) / 256, 256>>>(hstate, Wl, bl, out);
}

// round 3
// speedup vs baseline: 2.5096x; 1.5496x over previous
#include <cuda_runtime.h>
#include <cstdint>

// Problem constants (fixed shapes)
#define N_NODES 50000
#define T_STEPS 12
#define F_IN    128
#define HEADS   4
#define FILT    32
#define DDIM    128          // HEADS*FILT
#define E_EDGES 800000
#define NEG_SLOPE 0.2f
#define D3      (3 * DDIM)   // 384

// ---------------- scratch (device globals; no allocation in kernel_launch) ----------------
__device__ float d_h_feat[N_NODES * DDIM];     // h = x_t @ W_gat
__device__ float d_alS[N_NODES * HEADS];
__device__ float d_alD[N_NODES * HEADS];
__device__ float d_denom[N_NODES * HEADS];
__device__ float d_acc[N_NODES * DDIM];
__device__ float d_g[N_NODES * DDIM];          // relu'd GAT output
__device__ float d_gi[N_NODES * D3];
__device__ float d_gh[N_NODES * D3];
__device__ float d_hstate[N_NODES * DDIM];
__device__ float d_WihT[DDIM * D3];            // [k][j]
__device__ float d_WhhT[DDIM * D3];

// ---------------- small utility kernels ----------------
__global__ void zero_kernel(float* p, int n) {
    int i = blockIdx.x * blockDim.x + threadIdx.x;
    if (i < n) p[i] = 0.0f;
}

// WT[k*D3 + j] = W[j*DDIM + k]   (W is [3D, D] row-major)
__global__ void transpose_w(const float* __restrict__ W, float* __restrict__ WT) {
    int idx = blockIdx.x * blockDim.x + threadIdx.x;
    if (idx < D3 * DDIM) {
        int j = idx / DDIM;
        int k = idx - j * DDIM;
        WT[k * D3 + j] = W[idx];
    }
}

// ---------------- tf32 tensor-core GEMM ----------------
// C[m][c] = sum_k A[m][k] * W[k][c] (+bias[c]),  K = 128 fixed.
// Block tile 128x128, KC=32. 8 warps, each 32 rows x 64 cols via 2x8 m16n8k8.
// ATT=true (GAT path, NO==128, grid.y==1): fused attention-logit epilogue —
// writes alS/alD/denom and self-loop acc = w*h, plus h itself.

__device__ __forceinline__ float tf32r(float x) {
    uint32_t u;
    asm("cvt.rna.tf32.f32 %0, %1;" : "=r"(u) : "f"(x));
    return __uint_as_float(u);
}

__device__ __forceinline__ void mma16n8k8(float* c, const uint32_t* a, const uint32_t* b) {
    asm volatile(
        "mma.sync.aligned.m16n8k8.row.col.f32.tf32.tf32.f32 "
        "{%0,%1,%2,%3}, {%4,%5,%6,%7}, {%8,%9}, {%0,%1,%2,%3};\n"
        : "+f"(c[0]), "+f"(c[1]), "+f"(c[2]), "+f"(c[3])
        : "r"(a[0]), "r"(a[1]), "r"(a[2]), "r"(a[3]), "r"(b[0]), "r"(b[1]));
}

template <bool ATT>
__global__ __launch_bounds__(256, 2) void gemm_tf32(
    const float* __restrict__ A, int lda, int M,
    const float* __restrict__ W, int NO,
    const float* __restrict__ bias,
    float* __restrict__ C,
    const float* __restrict__ a_src, const float* __restrict__ a_dst,
    float* __restrict__ alS, float* __restrict__ alD,
    float* __restrict__ denom, float* __restrict__ acc)
{
    __shared__ float As[128][36];   // [m][k]
    __shared__ float Ws[32][132];   // [k][n]
    __shared__ float sS[128 * HEADS];   // per-(row,head) src logits (ATT)
    __shared__ float sD[128 * HEADS];

    const int tid  = threadIdx.x;
    const int lane = tid & 31;
    const int wid  = tid >> 5;
    const int wm   = (wid & 3) * 32;   // warp row base within block
    const int wn   = (wid >> 2) * 64;  // warp col base within block
    const int row0 = blockIdx.x * 128;
    const int c0   = blockIdx.y * 128;

    float cacc[2][8][4];
#pragma unroll
    for (int mf = 0; mf < 2; mf++)
#pragma unroll
        for (int nf = 0; nf < 8; nf++)
#pragma unroll
            for (int q = 0; q < 4; q++) cacc[mf][nf][q] = 0.0f;

    const int lq = lane >> 2;   // 0..7
    const int lr = lane & 3;    // 0..3

    if (ATT) {
        if (tid < 128 * HEADS / 2) { sS[tid] = 0.f; sS[tid + 256] = 0.f;
                                     sD[tid] = 0.f; sD[tid + 256] = 0.f; }
    }

    for (int k0 = 0; k0 < 128; k0 += 32) {
        __syncthreads();
        // A tile: 128 rows x 32 k  (1024 float4 slots, 4 per thread)
#pragma unroll
        for (int i = 0; i < 4; i++) {
            int f = tid + i * 256;
            int r = f >> 3, kq = f & 7;
            int gr = row0 + r;
            float4 v = make_float4(0.f, 0.f, 0.f, 0.f);
            if (gr < M) v = *(const float4*)&A[(long)gr * lda + k0 + kq * 4];
            float4 cv = make_float4(tf32r(v.x), tf32r(v.y), tf32r(v.z), tf32r(v.w));
            *(float4*)&As[r][kq * 4] = cv;
        }
        // W tile: 32 k x 128 cols (1024 float4 slots, 4 per thread)
#pragma unroll
        for (int i = 0; i < 4; i++) {
            int f = tid + i * 256;
            int kk = f >> 5, c4 = f & 31;
            float4 v = *(const float4*)&W[(long)(k0 + kk) * NO + c0 + c4 * 4];
            float4 cv = make_float4(tf32r(v.x), tf32r(v.y), tf32r(v.z), tf32r(v.w));
            *(float4*)&Ws[kk][c4 * 4] = cv;
        }
        __syncthreads();

#pragma unroll
        for (int s = 0; s < 4; s++) {
            const int ks = s * 8;
            uint32_t af[2][4];
#pragma unroll
            for (int mf = 0; mf < 2; mf++) {
                int r = wm + mf * 16 + lq;
                int kc = ks + lr;
                af[mf][0] = __float_as_uint(As[r][kc]);
                af[mf][1] = __float_as_uint(As[r + 8][kc]);
                af[mf][2] = __float_as_uint(As[r][kc + 4]);
                af[mf][3] = __float_as_uint(As[r + 8][kc + 4]);
            }
            uint32_t bf[8][2];
#pragma unroll
            for (int nf = 0; nf < 8; nf++) {
                int cc = wn + nf * 8 + lq;
                int kr = ks + lr;
                bf[nf][0] = __float_as_uint(Ws[kr][cc]);
                bf[nf][1] = __float_as_uint(Ws[kr + 4][cc]);
            }
#pragma unroll
            for (int mf = 0; mf < 2; mf++)
#pragma unroll
                for (int nf = 0; nf < 8; nf++)
                    mma16n8k8(cacc[mf][nf], af[mf], bf[nf]);
        }
    }

    if (!ATT) {
        // epilogue: bias + store
#pragma unroll
        for (int mf = 0; mf < 2; mf++) {
            int r_b = row0 + wm + mf * 16 + lq;
#pragma unroll
            for (int nf = 0; nf < 8; nf++) {
                int cc = c0 + wn + nf * 8 + lr * 2;
                float b0 = bias ? bias[cc] : 0.0f;
                float b1 = bias ? bias[cc + 1] : 0.0f;
                if (r_b < M) {
                    float2 o = make_float2(cacc[mf][nf][0] + b0, cacc[mf][nf][1] + b1);
                    *(float2*)&C[(long)r_b * NO + cc] = o;
                }
                if (r_b + 8 < M) {
                    float2 o = make_float2(cacc[mf][nf][2] + b0, cacc[mf][nf][3] + b1);
                    *(float2*)&C[(long)(r_b + 8) * NO + cc] = o;
                }
            }
        }
        return;
    }

    // ===== ATT epilogue: h store + attention logits + self-loop init =====
    // Thread owns cols cc, cc+1 for nf in 0..7 (cc = wn + nf*8 + lr*2), 4 rows.
    // Accumulate per-(row,head) partial dots with a_src/a_dst into smem.
    __syncthreads();   // sS/sD init visible; mainloop reads of As/Ws done
    {
        // preload attention vectors for this thread's 16 cols
        float aSv[8][2], aDv[8][2];
#pragma unroll
        for (int nf = 0; nf < 8; nf++) {
            int cc = wn + nf * 8 + lr * 2;
            aSv[nf][0] = a_src[cc];     aSv[nf][1] = a_src[cc + 1];
            aDv[nf][0] = a_dst[cc];     aDv[nf][1] = a_dst[cc + 1];
        }
#pragma unroll
        for (int mf = 0; mf < 2; mf++) {
#pragma unroll
            for (int half = 0; half < 2; half++) {      // lq row / lq+8 row
                int lrow = wm + mf * 16 + lq + half * 8;
                // two head-sub-ranges: nf 0..3 -> head h0, nf 4..7 -> head h0+1
                int h0 = wn >> 5;
                float pS0 = 0.f, pD0 = 0.f, pS1 = 0.f, pD1 = 0.f;
#pragma unroll
                for (int nf = 0; nf < 4; nf++) {
                    float v0 = cacc[mf][nf][half * 2], v1 = cacc[mf][nf][half * 2 + 1];
                    pS0 += v0 * aSv[nf][0] + v1 * aSv[nf][1];
                    pD0 += v0 * aDv[nf][0] + v1 * aDv[nf][1];
                }
#pragma unroll
                for (int nf = 4; nf < 8; nf++) {
                    float v0 = cacc[mf][nf][half * 2], v1 = cacc[mf][nf][half * 2 + 1];
                    pS1 += v0 * aSv[nf][0] + v1 * aSv[nf][1];
                    pD1 += v0 * aDv[nf][0] + v1 * aDv[nf][1];
                }
                atomicAdd(&sS[lrow * HEADS + h0], pS0);
                atomicAdd(&sD[lrow * HEADS + h0], pD0);
                atomicAdd(&sS[lrow * HEADS + h0 + 1], pS1);
                atomicAdd(&sD[lrow * HEADS + h0 + 1], pD1);
            }
        }
    }
    __syncthreads();
    // per-(row,head): write alS/alD/denom; stash w back into sS
    for (int i = tid; i < 128 * HEADS; i += 256) {
        int lrow = i >> 2;
        int gr = row0 + lrow;
        if (gr < M) {
            float sg = sS[i], dg = sD[i];
            float v = sg + dg;
            float e = v > 0.0f ? v : NEG_SLOPE * v;
            float w = __expf(e);
            alS[(long)gr * HEADS + (i & 3)] = sg;
            alD[(long)gr * HEADS + (i & 3)] = dg;
            denom[(long)gr * HEADS + (i & 3)] = w;
            sD[i] = w;      // reuse sD as per-(row,head) weight
        }
    }
    __syncthreads();
    // store h and self-loop acc = w*h
#pragma unroll
    for (int mf = 0; mf < 2; mf++) {
        int lrow = wm + mf * 16 + lq;
#pragma unroll
        for (int nf = 0; nf < 8; nf++) {
            int cc = wn + nf * 8 + lr * 2;
            int head = cc >> 5;
            int r_b = row0 + lrow;
            if (r_b < M) {
                float w = sD[lrow * HEADS + head];
                float2 o = make_float2(cacc[mf][nf][0], cacc[mf][nf][1]);
                *(float2*)&C[(long)r_b * DDIM + cc] = o;
                float2 a = make_float2(o.x * w, o.y * w);
                *(float2*)&acc[(long)r_b * DDIM + cc] = a;
            }
            if (r_b + 8 < M) {
                float w = sD[(lrow + 8) * HEADS + head];
                float2 o = make_float2(cacc[mf][nf][2], cacc[mf][nf][3]);
                *(float2*)&C[(long)(r_b + 8) * DDIM + cc] = o;
                float2 a = make_float2(o.x * w, o.y * w);
                *(float2*)&acc[(long)(r_b + 8) * DDIM + cc] = a;
            }
        }
    }
}

// ---------------- edge pass: one warp per edge, vectorized RED ----------------
__device__ __forceinline__ void red_add_v4(float* addr, float a, float b, float c, float d) {
    asm volatile("red.global.add.v4.f32 [%0], {%1,%2,%3,%4};"
                 :: "l"(addr), "f"(a), "f"(b), "f"(c), "f"(d) : "memory");
}

__global__ __launch_bounds__(256) void edge_kernel(
    const int* __restrict__ src_arr, const int* __restrict__ dst_arr,
    const float* __restrict__ alS, const float* __restrict__ alD,
    const float* __restrict__ h,
    float* __restrict__ denom, float* __restrict__ acc)
{
    long gw = (long)blockIdx.x * (blockDim.x >> 5) + (threadIdx.x >> 5);
    if (gw >= E_EDGES) return;
    int lane = threadIdx.x & 31;
    int head = lane >> 3;

    int s = src_arr[gw];
    int d = dst_arr[gw];

    float v = alS[s * HEADS + head] + alD[d * HEADS + head];
    float e = v > 0.0f ? v : NEG_SLOPE * v;
    float w = __expf(e);

    if ((lane & 7) == 0) atomicAdd(&denom[d * HEADS + head], w);

    float4 hv = ((const float4*)h)[s * 32 + lane];
    red_add_v4(&acc[d * DDIM + lane * 4], w * hv.x, w * hv.y, w * hv.z, w * hv.w);
}

// ---------------- finalize GAT: g = relu(acc/denom + b_gat) ----------------
__global__ void finalize_gat(
    const float* __restrict__ acc, const float* __restrict__ denom,
    const float* __restrict__ bg, float* __restrict__ g)
{
    int idx = blockIdx.x * blockDim.x + threadIdx.x;   // over N*32 float4s
    if (idx >= N_NODES * 32) return;
    int n = idx >> 5;
    int c4 = idx & 31;
    int head = c4 >> 3;
    float inv = 1.0f / (denom[n * HEADS + head] + 1e-16f);
    float4 a = ((const float4*)acc)[idx];
    float4 b = ((const float4*)bg)[c4];
    float4 o;
    o.x = fmaxf(a.x * inv + b.x, 0.0f);
    o.y = fmaxf(a.y * inv + b.y, 0.0f);
    o.z = fmaxf(a.z * inv + b.z, 0.0f);
    o.w = fmaxf(a.w * inv + b.w, 0.0f);
    ((float4*)g)[idx] = o;
}

// ---------------- GRU gates: h = (1-z)*n + z*h ----------------
__global__ void gru_gates(
    const float* __restrict__ gi, const float* __restrict__ gh,
    float* __restrict__ h)
{
    int idx = blockIdx.x * blockDim.x + threadIdx.x;   // over N*DDIM
    if (idx >= N_NODES * DDIM) return;
    int n = idx >> 7;
    int c = idx & 127;
    long base = (long)n * D3;
    float ir = gi[base + c],        hr = gh[base + c];
    float iz = gi[base + 128 + c],  hz = gh[base + 128 + c];
    float in_ = gi[base + 256 + c], hn = gh[base + 256 + c];
    float r = 1.0f / (1.0f + __expf(-(ir + hr)));
    float z = 1.0f / (1.0f + __expf(-(iz + hz)));
    float nn = tanhf(in_ + r * hn);
    h[idx] = (1.0f - z) * nn + z * h[idx];
}

// ---------------- final linear: out[n] = h[n] . W_lin + b_lin ----------------
__global__ __launch_bounds__(256) void final_linear(
    const float* __restrict__ h, const float* __restrict__ Wl,
    const float* __restrict__ bl, float* __restrict__ out)
{
    int warp = (blockIdx.x * blockDim.x + threadIdx.x) >> 5;
    int lane = threadIdx.x & 31;
    if (warp >= N_NODES) return;
    float4 hv = ((const float4*)h)[warp * 32 + lane];
    float4 wv = ((const float4*)Wl)[lane];
    float s = hv.x * wv.x + hv.y * wv.y + hv.z * wv.z + hv.w * wv.w;
#pragma unroll
    for (int off = 16; off > 0; off >>= 1)
        s += __shfl_down_sync(0xffffffffu, s, off);
    if (lane == 0) out[warp] = s + bl[0];
}

// ---------------- launcher ----------------
extern "C" void kernel_launch(void* const* d_in, const int* in_sizes, int n_in,
                              void* d_out, int out_size)
{
    const float* x   = (const float*)d_in[0];   // [N,T,F_IN]
    const int*   ei  = (const int*)d_in[1];     // [T,2,E]
    const float* Wg  = (const float*)d_in[2];   // [128,128]
    const float* as  = (const float*)d_in[3];   // [4,32]
    const float* ad  = (const float*)d_in[4];   // [4,32]
    const float* bg  = (const float*)d_in[5];   // [128]
    const float* Wih = (const float*)d_in[6];   // [384,128]
    const float* Whh = (const float*)d_in[7];   // [384,128]
    const float* bih = (const float*)d_in[8];   // [384]
    const float* bhh = (const float*)d_in[9];   // [384]
    const float* Wl  = (const float*)d_in[10];  // [1,128]
    const float* bl  = (const float*)d_in[11];  // [1]
    float* out = (float*)d_out;

    float *h_feat, *alS, *alD, *denom, *acc, *g, *gi, *gh, *hstate, *WihT, *WhhT;
    cudaGetSymbolAddress((void**)&h_feat, d_h_feat);
    cudaGetSymbolAddress((void**)&alS,    d_alS);
    cudaGetSymbolAddress((void**)&alD,    d_alD);
    cudaGetSymbolAddress((void**)&denom,  d_denom);
    cudaGetSymbolAddress((void**)&acc,    d_acc);
    cudaGetSymbolAddress((void**)&g,      d_g);
    cudaGetSymbolAddress((void**)&gi,     d_gi);
    cudaGetSymbolAddress((void**)&gh,     d_gh);
    cudaGetSymbolAddress((void**)&hstate, d_hstate);
    cudaGetSymbolAddress((void**)&WihT,   d_WihT);
    cudaGetSymbolAddress((void**)&WhhT,   d_WhhT);

    const int GX = (N_NODES + 127) / 128;   // 391

    // prologue: zero hidden state, transpose GRU weights
    zero_kernel<<<(N_NODES * DDIM + 255) / 256, 256>>>(hstate, N_NODES * DDIM);
    transpose_w<<<(D3 * DDIM + 255) / 256, 256>>>(Wih, WihT);
    transpose_w<<<(D3 * DDIM + 255) / 256, 256>>>(Whh, WhhT);

    for (int t = 0; t < T_STEPS; t++) {
        // 1) h = x_t @ W_gat  (+ fused attention logits + self-loop init)
        gemm_tf32<true><<<dim3(GX, 1), 256>>>(
            x + (long)t * F_IN, T_STEPS * F_IN, N_NODES, Wg, DDIM, nullptr, h_feat,
            as, ad, alS, alD, denom, acc);

        // 2) single edge pass (unnormalized softmax accumulation)
        const int* src = ei + (long)t * 2 * E_EDGES;
        const int* dst = src + E_EDGES;
        edge_kernel<<<(E_EDGES * 32 + 255) / 256, 256>>>(src, dst, alS, alD, h_feat, denom, acc);

        // 3) g = relu(acc/denom + b_gat)
        finalize_gat<<<(N_NODES * 32 + 255) / 256, 256>>>(acc, denom, bg, g);

        // 4) gi = g @ W_ih.T + b_ih ;  gh = h @ W_hh.T + b_hh  (tf32 tensor cores)
        gemm_tf32<false><<<dim3(GX, 3), 256>>>(g, DDIM, N_NODES, WihT, D3, bih, gi,
                                               nullptr, nullptr, nullptr, nullptr, nullptr, nullptr);
        gemm_tf32<false><<<dim3(GX, 3), 256>>>(hstate, DDIM, N_NODES, WhhT, D3, bhh, gh,
                                               nullptr, nullptr, nullptr, nullptr, nullptr, nullptr);

        // 5) GRU update
        gru_gates<<<(N_NODES * DDIM + 255) / 256, 256>>>(gi, gh, hstate);
    }

    // final projection
    final_linear<<<(N_NODES * 32 + 255) / 256, 256>>>(hstate, Wl, bl, out);
}

// round 4
// speedup vs baseline: 2.7233x; 1.0852x over previous
#include <cuda_runtime.h>
#include <cstdint>

// Problem constants (fixed shapes)
#define N_NODES 50000
#define T_STEPS 12
#define F_IN    128
#define HEADS   4
#define FILT    32
#define DDIM    128          // HEADS*FILT
#define E_EDGES 800000
#define NEG_SLOPE 0.2f
#define D3      (3 * DDIM)   // 384

// ---------------- scratch (device globals; no allocation in kernel_launch) ----------------
__device__ float d_h_feat[N_NODES * DDIM];     // h = x_t @ W_gat (fp32 accum)
__device__ float d_alS[N_NODES * HEADS];
__device__ float d_alD[N_NODES * HEADS];
__device__ float d_denom[N_NODES * HEADS];
__device__ float d_acc[N_NODES * DDIM];
__device__ float d_g[N_NODES * DDIM];          // relu'd GAT output (tf32-rounded)
__device__ float d_gi[N_NODES * D3];
__device__ float d_gh[N_NODES * D3];
__device__ float d_hstate[N_NODES * DDIM];     // exact fp32 GRU state
__device__ float d_h32[N_NODES * DDIM];        // tf32-rounded copy (GEMM input)
__device__ float d_WihT[DDIM * D3];            // [k][j], tf32-rounded
__device__ float d_WhhT[DDIM * D3];

__device__ __forceinline__ float tf32r(float x) {
    uint32_t u;
    asm("cvt.rna.tf32.f32 %0, %1;" : "=r"(u) : "f"(x));
    return __uint_as_float(u);
}

__device__ __forceinline__ void mma16n8k8(float* c, const uint32_t* a, const uint32_t* b) {
    asm volatile(
        "mma.sync.aligned.m16n8k8.row.col.f32.tf32.tf32.f32 "
        "{%0,%1,%2,%3}, {%4,%5,%6,%7}, {%8,%9}, {%0,%1,%2,%3};\n"
        : "+f"(c[0]), "+f"(c[1]), "+f"(c[2]), "+f"(c[3])
        : "r"(a[0]), "r"(a[1]), "r"(a[2]), "r"(a[3]), "r"(b[0]), "r"(b[1]));
}

__device__ __forceinline__ void cp_async16(uint32_t saddr, const void* gptr, int srcsize) {
    asm volatile("cp.async.cg.shared.global [%0], [%1], 16, %2;"
                 :: "r"(saddr), "l"(gptr), "r"(srcsize));
}

// ---------------- small utility kernels ----------------
__global__ void zero_kernel(float* p, float* q, int n) {
    int i = blockIdx.x * blockDim.x + threadIdx.x;
    if (i < n) { p[i] = 0.0f; q[i] = 0.0f; }
}

// WT[k*D3 + j] = tf32(W[j*DDIM + k])   (W is [3D, D] row-major)
__global__ void transpose_w(const float* __restrict__ W, float* __restrict__ WT) {
    int idx = blockIdx.x * blockDim.x + threadIdx.x;
    if (idx < D3 * DDIM) {
        int j = idx / DDIM;
        int k = idx - j * DDIM;
        WT[k * D3 + j] = tf32r(W[idx]);
    }
}

// ---------------- GAT GEMM + fused attention-logit epilogue ----------------
// C[m][c] = sum_k A[m][k]*W[k][c]; writes h, alS/alD/denom, self-loop acc=w*h.
__global__ __launch_bounds__(256, 2) void gemm_att(
    const float* __restrict__ A, int lda, int M,
    const float* __restrict__ W,
    float* __restrict__ C,
    const float* __restrict__ a_src, const float* __restrict__ a_dst,
    float* __restrict__ alS, float* __restrict__ alD,
    float* __restrict__ denom, float* __restrict__ acc)
{
    __shared__ float As[128][36];   // [m][k]
    __shared__ float Ws[32][132];   // [k][n]
    __shared__ float sS[128 * HEADS];
    __shared__ float sD[128 * HEADS];

    const int tid  = threadIdx.x;
    const int lane = tid & 31;
    const int wid  = tid >> 5;
    const int wm   = (wid & 3) * 32;
    const int wn   = (wid >> 2) * 64;
    const int row0 = blockIdx.x * 128;

    float cacc[2][8][4];
#pragma unroll
    for (int mf = 0; mf < 2; mf++)
#pragma unroll
        for (int nf = 0; nf < 8; nf++)
#pragma unroll
            for (int q = 0; q < 4; q++) cacc[mf][nf][q] = 0.0f;

    const int lq = lane >> 2;
    const int lr = lane & 3;

    if (tid < 128 * HEADS / 2) { sS[tid] = 0.f; sS[tid + 256] = 0.f;
                                 sD[tid] = 0.f; sD[tid + 256] = 0.f; }

    for (int k0 = 0; k0 < 128; k0 += 32) {
        __syncthreads();
#pragma unroll
        for (int i = 0; i < 4; i++) {
            int f = tid + i * 256;
            int r = f >> 3, kq = f & 7;
            int gr = row0 + r;
            float4 v = make_float4(0.f, 0.f, 0.f, 0.f);
            if (gr < M) v = *(const float4*)&A[(long)gr * lda + k0 + kq * 4];
            float4 cv = make_float4(tf32r(v.x), tf32r(v.y), tf32r(v.z), tf32r(v.w));
            *(float4*)&As[r][kq * 4] = cv;
        }
#pragma unroll
        for (int i = 0; i < 4; i++) {
            int f = tid + i * 256;
            int kk = f >> 5, c4 = f & 31;
            float4 v = *(const float4*)&W[(long)(k0 + kk) * DDIM + c4 * 4];
            float4 cv = make_float4(tf32r(v.x), tf32r(v.y), tf32r(v.z), tf32r(v.w));
            *(float4*)&Ws[kk][c4 * 4] = cv;
        }
        __syncthreads();

#pragma unroll
        for (int s = 0; s < 4; s++) {
            const int ks = s * 8;
            uint32_t af[2][4];
#pragma unroll
            for (int mf = 0; mf < 2; mf++) {
                int r = wm + mf * 16 + lq;
                int kc = ks + lr;
                af[mf][0] = __float_as_uint(As[r][kc]);
                af[mf][1] = __float_as_uint(As[r + 8][kc]);
                af[mf][2] = __float_as_uint(As[r][kc + 4]);
                af[mf][3] = __float_as_uint(As[r + 8][kc + 4]);
            }
            uint32_t bf[8][2];
#pragma unroll
            for (int nf = 0; nf < 8; nf++) {
                int cc = wn + nf * 8 + lq;
                int kr = ks + lr;
                bf[nf][0] = __float_as_uint(Ws[kr][cc]);
                bf[nf][1] = __float_as_uint(Ws[kr + 4][cc]);
            }
#pragma unroll
            for (int mf = 0; mf < 2; mf++)
#pragma unroll
                for (int nf = 0; nf < 8; nf++)
                    mma16n8k8(cacc[mf][nf], af[mf], bf[nf]);
        }
    }

    // ===== fused attention epilogue =====
    __syncthreads();
    {
        float aSv[8][2], aDv[8][2];
#pragma unroll
        for (int nf = 0; nf < 8; nf++) {
            int cc = wn + nf * 8 + lr * 2;
            aSv[nf][0] = a_src[cc];     aSv[nf][1] = a_src[cc + 1];
            aDv[nf][0] = a_dst[cc];     aDv[nf][1] = a_dst[cc + 1];
        }
#pragma unroll
        for (int mf = 0; mf < 2; mf++) {
#pragma unroll
            for (int half = 0; half < 2; half++) {
                int lrow = wm + mf * 16 + lq + half * 8;
                int h0 = wn >> 5;
                float pS0 = 0.f, pD0 = 0.f, pS1 = 0.f, pD1 = 0.f;
#pragma unroll
                for (int nf = 0; nf < 4; nf++) {
                    float v0 = cacc[mf][nf][half * 2], v1 = cacc[mf][nf][half * 2 + 1];
                    pS0 += v0 * aSv[nf][0] + v1 * aSv[nf][1];
                    pD0 += v0 * aDv[nf][0] + v1 * aDv[nf][1];
                }
#pragma unroll
                for (int nf = 4; nf < 8; nf++) {
                    float v0 = cacc[mf][nf][half * 2], v1 = cacc[mf][nf][half * 2 + 1];
                    pS1 += v0 * aSv[nf][0] + v1 * aSv[nf][1];
                    pD1 += v0 * aDv[nf][0] + v1 * aDv[nf][1];
                }
                atomicAdd(&sS[lrow * HEADS + h0], pS0);
                atomicAdd(&sD[lrow * HEADS + h0], pD0);
                atomicAdd(&sS[lrow * HEADS + h0 + 1], pS1);
                atomicAdd(&sD[lrow * HEADS + h0 + 1], pD1);
            }
        }
    }
    __syncthreads();
    for (int i = tid; i < 128 * HEADS; i += 256) {
        int lrow = i >> 2;
        int gr = row0 + lrow;
        if (gr < M) {
            float sg = sS[i], dg = sD[i];
            float v = sg + dg;
            float e = v > 0.0f ? v : NEG_SLOPE * v;
            float w = __expf(e);
            alS[(long)gr * HEADS + (i & 3)] = sg;
            alD[(long)gr * HEADS + (i & 3)] = dg;
            denom[(long)gr * HEADS + (i & 3)] = w;
            sD[i] = w;
        }
    }
    __syncthreads();
#pragma unroll
    for (int mf = 0; mf < 2; mf++) {
        int lrow = wm + mf * 16 + lq;
#pragma unroll
        for (int nf = 0; nf < 8; nf++) {
            int cc = wn + nf * 8 + lr * 2;
            int head = cc >> 5;
            int r_b = row0 + lrow;
            if (r_b < M) {
                float w = sD[lrow * HEADS + head];
                float2 o = make_float2(cacc[mf][nf][0], cacc[mf][nf][1]);
                *(float2*)&C[(long)r_b * DDIM + cc] = o;
                *(float2*)&acc[(long)r_b * DDIM + cc] = make_float2(o.x * w, o.y * w);
            }
            if (r_b + 8 < M) {
                float w = sD[(lrow + 8) * HEADS + head];
                float2 o = make_float2(cacc[mf][nf][2], cacc[mf][nf][3]);
                *(float2*)&C[(long)(r_b + 8) * DDIM + cc] = o;
                *(float2*)&acc[(long)(r_b + 8) * DDIM + cc] = make_float2(o.x * w, o.y * w);
            }
        }
    }
}

// ---------------- pipelined GRU GEMM: A[M,128] @ W[128,NO] + bias ----------------
// Inputs pre-rounded to tf32. 2-stage cp.async double buffer. K=128, KC=32.
#define AS_STAGE (128 * 36)
#define WS_STAGE (32 * 132)
#define PIPE_SMEM_BYTES ((2 * AS_STAGE + 2 * WS_STAGE) * 4)

__global__ __launch_bounds__(256, 2) void gemm_tf32_pipe(
    const float* __restrict__ A, int M,
    const float* __restrict__ W, int NO,
    const float* __restrict__ bias,
    float* __restrict__ C)
{
    extern __shared__ float sm[];
    float* AsBase = sm;                       // [2][128][36]
    float* WsBase = sm + 2 * AS_STAGE;        // [2][32][132]

    const int tid  = threadIdx.x;
    const int lane = tid & 31;
    const int wid  = tid >> 5;
    const int wm   = (wid & 3) * 32;
    const int wn   = (wid >> 2) * 64;
    const int row0 = blockIdx.x * 128;
    const int c0   = blockIdx.y * 128;
    const int lq   = lane >> 2;
    const int lr   = lane & 3;

    float cacc[2][8][4];
#pragma unroll
    for (int mf = 0; mf < 2; mf++)
#pragma unroll
        for (int nf = 0; nf < 8; nf++)
#pragma unroll
            for (int q = 0; q < 4; q++) cacc[mf][nf][q] = 0.0f;

    const uint32_t sA = (uint32_t)__cvta_generic_to_shared(AsBase);
    const uint32_t sW = (uint32_t)__cvta_generic_to_shared(WsBase);

    // precompute per-thread load coords
    const int ar = tid >> 3;           // base row of A loads (tid/8), +32*i
    const int akq = tid & 7;           // A k-quad
    const int wkk = tid >> 5;          // base k of W loads, +8*i
    const int wc4 = tid & 31;          // W col-quad

#define PREFETCH(it_)                                                              \
    {                                                                              \
        int k0_ = (it_) * 32;                                                      \
        int st_ = (it_) & 1;                                                       \
        _Pragma("unroll")                                                          \
        for (int i = 0; i < 4; i++) {                                              \
            int r_ = ar + i * 32;                                                  \
            int gr_ = row0 + r_;                                                   \
            uint32_t sa_ = sA + (uint32_t)((st_ * AS_STAGE + r_ * 36 + akq * 4) * 4); \
            const float* gp_ = &A[(long)(gr_ < M ? gr_ : 0) * 128 + k0_ + akq * 4]; \
            cp_async16(sa_, gp_, gr_ < M ? 16 : 0);                                \
        }                                                                          \
        _Pragma("unroll")                                                          \
        for (int i = 0; i < 4; i++) {                                              \
            int kk_ = wkk + i * 8;                                                 \
            uint32_t sa_ = sW + (uint32_t)((st_ * WS_STAGE + kk_ * 132 + wc4 * 4) * 4); \
            const float* gp_ = &W[(long)(k0_ + kk_) * NO + c0 + wc4 * 4];           \
            cp_async16(sa_, gp_, 16);                                              \
        }                                                                          \
        asm volatile("cp.async.commit_group;");                                    \
    }

    PREFETCH(0);
#pragma unroll
    for (int it = 0; it < 4; it++) {
        if (it < 3) {
            PREFETCH(it + 1);
            asm volatile("cp.async.wait_group 1;");
        } else {
            asm volatile("cp.async.wait_group 0;");
        }
        __syncthreads();
        const float* Asc = AsBase + (it & 1) * AS_STAGE;
        const float* Wsc = WsBase + (it & 1) * WS_STAGE;
#pragma unroll
        for (int s = 0; s < 4; s++) {
            const int ks = s * 8;
            uint32_t af[2][4];
#pragma unroll
            for (int mf = 0; mf < 2; mf++) {
                int r = wm + mf * 16 + lq;
                int kc = ks + lr;
                af[mf][0] = __float_as_uint(Asc[r * 36 + kc]);
                af[mf][1] = __float_as_uint(Asc[(r + 8) * 36 + kc]);
                af[mf][2] = __float_as_uint(Asc[r * 36 + kc + 4]);
                af[mf][3] = __float_as_uint(Asc[(r + 8) * 36 + kc + 4]);
            }
            uint32_t bf[8][2];
#pragma unroll
            for (int nf = 0; nf < 8; nf++) {
                int cc = wn + nf * 8 + lq;
                int kr = ks + lr;
                bf[nf][0] = __float_as_uint(Wsc[kr * 132 + cc]);
                bf[nf][1] = __float_as_uint(Wsc[(kr + 4) * 132 + cc]);
            }
#pragma unroll
            for (int mf = 0; mf < 2; mf++)
#pragma unroll
                for (int nf = 0; nf < 8; nf++)
                    mma16n8k8(cacc[mf][nf], af[mf], bf[nf]);
        }
        __syncthreads();
    }
#undef PREFETCH

#pragma unroll
    for (int mf = 0; mf < 2; mf++) {
        int r_b = row0 + wm + mf * 16 + lq;
#pragma unroll
        for (int nf = 0; nf < 8; nf++) {
            int cc = c0 + wn + nf * 8 + lr * 2;
            float b0 = bias[cc];
            float b1 = bias[cc + 1];
            if (r_b < M)
                *(float2*)&C[(long)r_b * NO + cc] =
                    make_float2(cacc[mf][nf][0] + b0, cacc[mf][nf][1] + b1);
            if (r_b + 8 < M)
                *(float2*)&C[(long)(r_b + 8) * NO + cc] =
                    make_float2(cacc[mf][nf][2] + b0, cacc[mf][nf][3] + b1);
        }
    }
}

// ---------------- edge pass: one warp per edge, vectorized RED ----------------
__device__ __forceinline__ void red_add_v4(float* addr, float a, float b, float c, float d) {
    asm volatile("red.global.add.v4.f32 [%0], {%1,%2,%3,%4};"
                 :: "l"(addr), "f"(a), "f"(b), "f"(c), "f"(d) : "memory");
}

__global__ __launch_bounds__(256) void edge_kernel(
    const int* __restrict__ src_arr, const int* __restrict__ dst_arr,
    const float* __restrict__ alS, const float* __restrict__ alD,
    const float* __restrict__ h,
    float* __restrict__ denom, float* __restrict__ acc)
{
    long gw = (long)blockIdx.x * (blockDim.x >> 5) + (threadIdx.x >> 5);
    if (gw >= E_EDGES) return;
    int lane = threadIdx.x & 31;
    int head = lane >> 3;

    int s = src_arr[gw];
    int d = dst_arr[gw];

    float v = alS[s * HEADS + head] + alD[d * HEADS + head];
    float e = v > 0.0f ? v : NEG_SLOPE * v;
    float w = __expf(e);

    if ((lane & 7) == 0) atomicAdd(&denom[d * HEADS + head], w);

    float4 hv = ((const float4*)h)[s * 32 + lane];
    red_add_v4(&acc[d * DDIM + lane * 4], w * hv.x, w * hv.y, w * hv.z, w * hv.w);
}

// ---------------- finalize GAT: g = tf32(relu(acc/denom + b_gat)) ----------------
__global__ void finalize_gat(
    const float* __restrict__ acc, const float* __restrict__ denom,
    const float* __restrict__ bg, float* __restrict__ g)
{
    int idx = blockIdx.x * blockDim.x + threadIdx.x;
    if (idx >= N_NODES * 32) return;
    int n = idx >> 5;
    int c4 = idx & 31;
    int head = c4 >> 3;
    float inv = 1.0f / (denom[n * HEADS + head] + 1e-16f);
    float4 a = ((const float4*)acc)[idx];
    float4 b = ((const float4*)bg)[c4];
    float4 o;
    o.x = tf32r(fmaxf(a.x * inv + b.x, 0.0f));
    o.y = tf32r(fmaxf(a.y * inv + b.y, 0.0f));
    o.z = tf32r(fmaxf(a.z * inv + b.z, 0.0f));
    o.w = tf32r(fmaxf(a.w * inv + b.w, 0.0f));
    ((float4*)g)[idx] = o;
}

// ---------------- GRU gates: h = (1-z)*n + z*h; also write tf32 copy ----------------
__global__ void gru_gates(
    const float* __restrict__ gi, const float* __restrict__ gh,
    float* __restrict__ h, float* __restrict__ h32)
{
    int idx = blockIdx.x * blockDim.x + threadIdx.x;   // over N*32 float4s
    if (idx >= N_NODES * 32) return;
    int n = idx >> 5;
    long base = (long)n * D3 + (idx & 31) * 4;
    float4 ir = *(const float4*)&gi[base];
    float4 hr = *(const float4*)&gh[base];
    float4 iz = *(const float4*)&gi[base + 128];
    float4 hz = *(const float4*)&gh[base + 128];
    float4 in_ = *(const float4*)&gi[base + 256];
    float4 hn = *(const float4*)&gh[base + 256];
    float4 hv = ((const float4*)h)[idx];
    float4 ho, h32o;
#pragma unroll
    for (int q = 0; q < 4; q++) {
        float irf = (&ir.x)[q], hrf = (&hr.x)[q];
        float izf = (&iz.x)[q], hzf = (&hz.x)[q];
        float inf = (&in_.x)[q], hnf = (&hn.x)[q];
        float hvf = (&hv.x)[q];
        float r = 1.0f / (1.0f + __expf(-(irf + hrf)));
        float z = 1.0f / (1.0f + __expf(-(izf + hzf)));
        float nn = tanhf(inf + r * hnf);
        float hnew = (1.0f - z) * nn + z * hvf;
        (&ho.x)[q] = hnew;
        (&h32o.x)[q] = tf32r(hnew);
    }
    ((float4*)h)[idx] = ho;
    ((float4*)h32)[idx] = h32o;
}

// ---------------- final linear ----------------
__global__ __launch_bounds__(256) void final_linear(
    const float* __restrict__ h, const float* __restrict__ Wl,
    const float* __restrict__ bl, float* __restrict__ out)
{
    int warp = (blockIdx.x * blockDim.x + threadIdx.x) >> 5;
    int lane = threadIdx.x & 31;
    if (warp >= N_NODES) return;
    float4 hv = ((const float4*)h)[warp * 32 + lane];
    float4 wv = ((const float4*)Wl)[lane];
    float s = hv.x * wv.x + hv.y * wv.y + hv.z * wv.z + hv.w * wv.w;
#pragma unroll
    for (int off = 16; off > 0; off >>= 1)
        s += __shfl_down_sync(0xffffffffu, s, off);
    if (lane == 0) out[warp] = s + bl[0];
}

// ---------------- launcher ----------------
extern "C" void kernel_launch(void* const* d_in, const int* in_sizes, int n_in,
                              void* d_out, int out_size)
{
    const float* x   = (const float*)d_in[0];
    const int*   ei  = (const int*)d_in[1];
    const float* Wg  = (const float*)d_in[2];
    const float* as  = (const float*)d_in[3];
    const float* ad  = (const float*)d_in[4];
    const float* bg  = (const float*)d_in[5];
    const float* Wih = (const float*)d_in[6];
    const float* Whh = (const float*)d_in[7];
    const float* bih = (const float*)d_in[8];
    const float* bhh = (const float*)d_in[9];
    const float* Wl  = (const float*)d_in[10];
    const float* bl  = (const float*)d_in[11];
    float* out = (float*)d_out;

    float *h_feat, *alS, *alD, *denom, *acc, *g, *gi, *gh, *hstate, *h32, *WihT, *WhhT;
    cudaGetSymbolAddress((void**)&h_feat, d_h_feat);
    cudaGetSymbolAddress((void**)&alS,    d_alS);
    cudaGetSymbolAddress((void**)&alD,    d_alD);
    cudaGetSymbolAddress((void**)&denom,  d_denom);
    cudaGetSymbolAddress((void**)&acc,    d_acc);
    cudaGetSymbolAddress((void**)&g,      d_g);
    cudaGetSymbolAddress((void**)&gi,     d_gi);
    cudaGetSymbolAddress((void**)&gh,     d_gh);
    cudaGetSymbolAddress((void**)&hstate, d_hstate);
    cudaGetSymbolAddress((void**)&h32,    d_h32);
    cudaGetSymbolAddress((void**)&WihT,   d_WihT);
    cudaGetSymbolAddress((void**)&WhhT,   d_WhhT);

    cudaFuncSetAttribute(gemm_tf32_pipe,
                         cudaFuncAttributeMaxDynamicSharedMemorySize, PIPE_SMEM_BYTES);

    const int GX = (N_NODES + 127) / 128;   // 391

    zero_kernel<<<(N_NODES * DDIM + 255) / 256, 256>>>(hstate, h32, N_NODES * DDIM);
    transpose_w<<<(D3 * DDIM + 255) / 256, 256>>>(Wih, WihT);
    transpose_w<<<(D3 * DDIM + 255) / 256, 256>>>(Whh, WhhT);

    for (int t = 0; t < T_STEPS; t++) {
        // 1) h = x_t @ W_gat (+ fused attention logits + self-loop init)
        gemm_att<<<GX, 256>>>(x + (long)t * F_IN, T_STEPS * F_IN, N_NODES, Wg, h_feat,
                              as, ad, alS, alD, denom, acc);

        // 2) edge pass (unnormalized softmax accumulation)
        const int* src = ei + (long)t * 2 * E_EDGES;
        const int* dst = src + E_EDGES;
        edge_kernel<<<(E_EDGES * 32 + 255) / 256, 256>>>(src, dst, alS, alD, h_feat, denom, acc);

        // 3) g = tf32(relu(acc/denom + b_gat))
        finalize_gat<<<(N_NODES * 32 + 255) / 256, 256>>>(acc, denom, bg, g);

        // 4) gi = g @ WihT + b_ih ; gh = h32 @ WhhT + b_hh  (pipelined tf32)
        gemm_tf32_pipe<<<dim3(GX, 3), 256, PIPE_SMEM_BYTES>>>(g, N_NODES, WihT, D3, bih, gi);
        gemm_tf32_pipe<<<dim3(GX, 3), 256, PIPE_SMEM_BYTES>>>(h32, N_NODES, WhhT, D3, bhh, gh);

        // 5) GRU update (writes exact h + tf32 copy)
        gru_gates<<<(N_NODES * 32 + 255) / 256, 256>>>(gi, gh, hstate, h32);
    }

    final_linear<<<(N_NODES * 32 + 255) / 256, 256>>>(hstate, Wl, bl, out);
}